// round 9
// baseline (speedup 1.0000x reference)
#include <cuda_runtime.h>
#include <cuda_fp16.h>
#include <cstdint>

#define BATCH 16
#define CIN   128
#define COUT  256
#define HW    56

__device__ __align__(16) __half    g_xh[BATCH * HW * HW * CIN];     // NHWC fp16 (12.8MB)
__device__ __align__(16) __half    g_wh[9 * COUT * CIN];            // [tap][o][c] fp16
__device__ __align__(16) unsigned  g_xq4[BATCH * HW * HW * 32];     // NHWC u8 quads (6.4MB)
__device__ __align__(16) unsigned  g_wq4[9 * COUT * 32];            // [tap][o][cq] u8 quads

__device__ __forceinline__ uint32_t smem_u32(const void* p) {
    uint32_t a;
    asm("{ .reg .u64 t; cvta.to.shared.u64 t, %1; cvt.u32.u64 %0, t; }" : "=r"(a) : "l"(p));
    return a;
}

// ---------------------------------------------------------------------------
// Kernel 1: x NCHW f32 -> NHWC {fp16, u8} quantized (smem transpose)
// ---------------------------------------------------------------------------
__global__ void __launch_bounds__(256) pack_x_kernel(const float* __restrict__ x) {
    __shared__ float tile[64][60];
    const int b = blockIdx.x / HW, h = blockIdx.x % HW;
    const int ch0 = blockIdx.y * 64;
    const int t = threadIdx.x;
#pragma unroll
    for (int j = 0; j < 4; ++j) {
        int idx = t + j * 256;
        if (idx >= 64 * 14) break;
        int c = idx / 14, f4 = idx % 14;
        float4 v = *(const float4*)&x[((b * CIN + ch0 + c) * HW + h) * HW + f4 * 4];
        tile[c][f4 * 4 + 0] = v.x; tile[c][f4 * 4 + 1] = v.y;
        tile[c][f4 * 4 + 2] = v.z; tile[c][f4 * 4 + 3] = v.w;
    }
    __syncthreads();
#pragma unroll
    for (int j = 0; j < 2; ++j) {
        int i = t + j * 256;
        if (i >= HW * 8) break;
        int chunk = i / HW, w = i % HW;
        int c0 = chunk * 8;
        float q[8];
#pragma unroll
        for (int k = 0; k < 8; ++k) {
            float v = rintf(tile[c0 + k][w] * 255.0f);
            q[k] = fminf(fmaxf(v, 0.0f), 255.0f);
        }
        uint4 vf;
        unsigned* pf = (unsigned*)&vf;
#pragma unroll
        for (int k = 0; k < 4; ++k) {
            __half2 h2 = __floats2half2_rn(q[2 * k], q[2 * k + 1]);
            pf[k] = *(unsigned*)&h2;
        }
        *(uint4*)&g_xh[((b * HW + h) * HW + w) * CIN + ch0 + c0] = vf;
        uint2 vu;
        vu.x = (unsigned)q[0] | ((unsigned)q[1] << 8) | ((unsigned)q[2] << 16) | ((unsigned)q[3] << 24);
        vu.y = (unsigned)q[4] | ((unsigned)q[5] << 8) | ((unsigned)q[6] << 16) | ((unsigned)q[7] << 24);
        *(uint2*)&g_xq4[((b * HW + h) * HW + w) * 32 + (ch0 + c0) / 4] = vu;
    }
}

// ---------------------------------------------------------------------------
// Kernel 2a/2b: pcilt[...,1] -> fp16 and u8 weight layouts
// ---------------------------------------------------------------------------
__global__ void pack_w_kernel(const float* __restrict__ pcilt) {
    int idx = blockIdx.x * 256 + threadIdx.x;
    if (idx >= 9 * COUT * CIN) return;
    int c   = idx % CIN;
    int o   = (idx / CIN) % COUT;
    int tap = idx / (CIN * COUT);
    long long p = (((long long)(o * CIN + c)) * 9 + tap) * 256 + 1;
    g_wh[(tap * COUT + o) * CIN + c] = __float2half_rn(pcilt[p]);
}
__global__ void pack_w8_kernel(const float* __restrict__ pcilt) {
    int idx = blockIdx.x * 256 + threadIdx.x;
    if (idx >= 9 * COUT * 32) return;
    int cq  = idx % 32;
    int o   = (idx / 32) % COUT;
    int tap = idx / (32 * COUT);
    unsigned v = 0;
#pragma unroll
    for (int k = 0; k < 4; ++k) {
        long long p = (((long long)(o * CIN + cq * 4 + k)) * 9 + tap) * 256 + 1;
        v |= ((unsigned)(int)rintf(pcilt[p])) << (8 * k);
    }
    g_wq4[(tap * COUT + o) * 32 + cq] = v;
}

// ---------------------------------------------------------------------------
// Kernel 3: hybrid conv. CTA = M128 (2 rows x 64) x N64, 384 threads:
//   warps 0-7 : HMMA, oc[0..47], 2-slot mbarrier W-f16 ring
//   warps 8-11: dp4a, oc[48..63], A/W u8 staged once in prologue
// ---------------------------------------------------------------------------
#define SX_STRIDE 272
#define SX_ROWS   258
#define SW_STRIDE 272
#define SMEM_SX   0
#define SMEM_WF   (SX_ROWS * SX_STRIDE)            // 70176
#define WF_SLOT   (48 * SW_STRIDE)                 // 13056
#define SMEM_XU   (SMEM_WF + 2 * WF_SLOT)          // 96288
#define XU_STRIDE 144
#define SMEM_WU   (SMEM_XU + SX_ROWS * XU_STRIDE)  // 133440
#define WU_STRIDE 144
#define SMEM_MB   (SMEM_WU + 9 * 16 * WU_STRIDE)   // 154176
#define SMEM_SZ   (SMEM_MB + 64)
#define OSTR      132

__device__ __forceinline__ void hmma(float* c, unsigned a0, unsigned a1, unsigned a2, unsigned a3,
                                     unsigned b0, unsigned b1) {
    asm volatile(
        "mma.sync.aligned.m16n8k16.row.col.f32.f16.f16.f32 "
        "{%0,%1,%2,%3}, {%4,%5,%6,%7}, {%8,%9}, {%0,%1,%2,%3};"
        : "+f"(c[0]), "+f"(c[1]), "+f"(c[2]), "+f"(c[3])
        : "r"(a0), "r"(a1), "r"(a2), "r"(a3), "r"(b0), "r"(b1));
}
#define LDSM4(r0, r1, r2, r3, addr) \
    asm volatile("ldmatrix.sync.aligned.m8n8.x4.shared.b16 {%0,%1,%2,%3}, [%4];" \
        : "=r"(r0), "=r"(r1), "=r"(r2), "=r"(r3) : "r"(addr))
#define LDSM2(r0, r1, addr) \
    asm volatile("ldmatrix.sync.aligned.m8n8.x2.shared.b16 {%0,%1}, [%2];" \
        : "=r"(r0), "=r"(r1) : "r"(addr))
#define CPASYNC(dst, src, sz) \
    asm volatile("cp.async.cg.shared.global [%0], [%1], 16, %2;" :: "r"(dst), "l"(src), "r"(sz))
#define MBAR_INIT(a, n) asm volatile("mbarrier.init.shared.b64 [%0], %1;" :: "r"(a), "r"(n) : "memory")
#define MBAR_ARRIVE(a)  asm volatile("mbarrier.arrive.shared.b64 _, [%0];" :: "r"(a) : "memory")
#define CP_MBAR_ARRIVE(a) \
    asm volatile("cp.async.mbarrier.arrive.noinc.shared.b64 [%0];" :: "r"(a) : "memory")
#define MBAR_WAIT(a, ph) do {                                                     \
    uint32_t _m = (a), _p = (uint32_t)(ph), _d;                                   \
    asm volatile("{ .reg .pred p; mbarrier.try_wait.parity.acquire.cta.shared::cta.b64 p, [%1], %2; selp.b32 %0,1,0,p; }" \
        : "=r"(_d) : "r"(_m), "r"(_p) : "memory");                                \
    if (!_d) {                                                                    \
        asm volatile("{ .reg .pred P1; WL_%=: mbarrier.try_wait.parity.acquire.cta.shared::cta.b64 P1, [%0], %1, 0x989680;" \
            " @P1 bra.uni WD_%=; bra.uni WL_%=; WD_%=: }" :: "r"(_m), "r"(_p) : "memory"); \
    } } while (0)

__global__ void __launch_bounds__(384, 1)
conv_hybrid_kernel(const float* __restrict__ bias, float* __restrict__ out) {
    extern __shared__ __align__(16) unsigned char smem[];
    const uint32_t sb = smem_u32(smem);

    const int t    = threadIdx.x;
    const int wid  = t >> 5;
    const int lane = t & 31;
    const int ocbase = blockIdx.x * 64;
    const int h0     = blockIdx.y * 2;
    const int b      = blockIdx.z;

    const uint32_t mb_full  = sb + SMEM_MB;
    const uint32_t mb_empty = sb + SMEM_MB + 16;

    if (t == 0) {
#pragma unroll
        for (int s = 0; s < 2; ++s) {
            MBAR_INIT(mb_full + s * 8, 256);
            MBAR_INIT(mb_empty + s * 8, 256);
        }
    }
    __syncthreads();

    // ---- Prologue staging ----
    // W-f16 ring slots 0,1 (HMMA threads only; 48 oc x 16 chunks = 768 each)
    if (t < 256) {
#pragma unroll
        for (int tap = 0; tap < 2; ++tap) {
            uint32_t wdst = sb + SMEM_WF + tap * WF_SLOT;
#pragma unroll
            for (int j = 0; j < 3; ++j) {
                int i = t + j * 256;
                int o = i >> 4, chunk = i & 15;
                CPASYNC(wdst + o * SW_STRIDE + chunk * 16,
                        &g_wh[(tap * COUT + ocbase + o) * CIN + chunk * 8], 16);
            }
            CP_MBAR_ARRIVE(mb_full + tap * 8);
        }
    }
    // A fp16 tile (all threads)
    for (int i = t; i < SX_ROWS * 16; i += 384) {
        int pixel = i >> 4, chunk = i & 15;
        int irow = pixel >> 6, col = pixel & 63;
        int h_in = h0 + irow - 1, w_in = col - 1;
        bool ok = (pixel < 256) && (h_in >= 0) && (h_in < HW) && (w_in >= 0) && (w_in < HW);
        const __half* src = ok ? &g_xh[((b * HW + h_in) * HW + w_in) * CIN + chunk * 8] : g_xh;
        CPASYNC(sb + SMEM_SX + pixel * SX_STRIDE + chunk * 16, src, ok ? 16 : 0);
    }
    // A u8 tile (258 px x 8 chunks)
    for (int i = t; i < SX_ROWS * 8; i += 384) {
        int pixel = i >> 3, chunk = i & 7;
        int irow = pixel >> 6, col = pixel & 63;
        int h_in = h0 + irow - 1, w_in = col - 1;
        bool ok = (pixel < 256) && (h_in >= 0) && (h_in < HW) && (w_in >= 0) && (w_in < HW);
        const unsigned* src = ok ? &g_xq4[((b * HW + h_in) * HW + w_in) * 32 + chunk * 4] : g_xq4;
        CPASYNC(sb + SMEM_XU + pixel * XU_STRIDE + chunk * 16, src, ok ? 16 : 0);
    }
    // W u8: all 9 taps x 16 oc x 8 chunks = 1152
    for (int i = t; i < 9 * 16 * 8; i += 384) {
        int chunk = i & 7, o = (i >> 3) & 15, tap = i >> 7;
        CPASYNC(sb + SMEM_WU + (tap * 16 + o) * WU_STRIDE + chunk * 16,
                &g_wq4[(tap * COUT + ocbase + 48 + o) * 32 + chunk * 4], 16);
    }
    asm volatile("cp.async.commit_group;");
    asm volatile("cp.async.wait_group 0;" ::: "memory");
    __syncthreads();

    if (wid < 8) {
        // =================== HMMA path: oc[0..47] ===================
        const int wm = (wid >> 1) * 32;
        const int wn = (wid & 1) * 24;

        float acc[2][3][4];
#pragma unroll
        for (int mt = 0; mt < 2; ++mt)
#pragma unroll
            for (int nt = 0; nt < 3; ++nt)
#pragma unroll
                for (int k = 0; k < 4; ++k) acc[mt][nt][k] = 0.0f;

        const int g = lane >> 3;
        const int a_lane = (((g & 1) * 8) + (lane & 7)) * SX_STRIDE + (g >> 1) * 16;
        const int b_lane = (((g >> 1) * 8) + (lane & 7)) * SW_STRIDE + (g & 1) * 16;

#pragma unroll 1
        for (int tap = 0; tap < 9; ++tap) {
            const int kh = tap / 3, kw = tap % 3;
            const int slot = tap & 1;
            const uint32_t swc = sb + SMEM_WF + slot * WF_SLOT;
            const uint32_t abase = sb + SMEM_SX + (kh * 64 + kw + wm) * SX_STRIDE + a_lane;
            const uint32_t bbase = swc + wn * SW_STRIDE + b_lane;

            MBAR_WAIT(mb_full + slot * 8, (tap >> 1) & 1);

#pragma unroll
            for (int ks = 0; ks < 8; ++ks) {
                const int koff = ks * 32;
                unsigned a[2][4], bf[3][2];
                LDSM4(a[0][0], a[0][1], a[0][2], a[0][3], abase + koff);
                LDSM4(a[1][0], a[1][1], a[1][2], a[1][3], abase + 16 * SX_STRIDE + koff);
                LDSM4(bf[0][0], bf[0][1], bf[1][0], bf[1][1], bbase + koff);
                LDSM2(bf[2][0], bf[2][1], bbase + 16 * SW_STRIDE + koff);
#pragma unroll
                for (int mt = 0; mt < 2; ++mt)
#pragma unroll
                    for (int nt = 0; nt < 3; ++nt)
                        hmma(acc[mt][nt], a[mt][0], a[mt][1], a[mt][2], a[mt][3],
                             bf[nt][0], bf[nt][1]);
            }

            MBAR_ARRIVE(mb_empty + slot * 8);

            if (tap <= 6) {
                MBAR_WAIT(mb_empty + slot * 8, (tap >> 1) & 1);
                uint32_t wdst = sb + SMEM_WF + slot * WF_SLOT;
#pragma unroll
                for (int j = 0; j < 3; ++j) {
                    int i = t + j * 256;
                    int o = i >> 4, chunk = i & 15;
                    CPASYNC(wdst + o * SW_STRIDE + chunk * 16,
                            &g_wh[((tap + 2) * COUT + ocbase + o) * CIN + chunk * 8], 16);
                }
                CP_MBAR_ARRIVE(mb_full + slot * 8);
            }
        }

        __syncthreads();   // join with dp4a warps; A region free for epilogue

        float* s_out = (float*)smem;
#pragma unroll
        for (int mt = 0; mt < 2; ++mt)
#pragma unroll
            for (int nt = 0; nt < 3; ++nt) {
                int row = wm + mt * 16 + (lane >> 2);
                int col = wn + nt * 8 + (lane & 3) * 2;
                s_out[col * OSTR + row]           = acc[mt][nt][0];
                s_out[(col + 1) * OSTR + row]     = acc[mt][nt][1];
                s_out[col * OSTR + row + 8]       = acc[mt][nt][2];
                s_out[(col + 1) * OSTR + row + 8] = acc[mt][nt][3];
            }
    } else {
        // =================== dp4a path: oc[48..63] ===================
        const int dwid = wid - 8;                 // 0..3 -> px block
        const int px0  = dwid * 32 + (lane & 7);  // +8p, p=0..3
        const int ocg  = lane >> 3;               // 0..3 -> oc = 48+ocg*4+o

        unsigned acc[4][4];
#pragma unroll
        for (int p = 0; p < 4; ++p)
#pragma unroll
            for (int o = 0; o < 4; ++o) acc[p][o] = 0u;

        const uint32_t wub = sb + SMEM_WU + ocg * 4 * WU_STRIDE;

#pragma unroll 1
        for (int tap = 0; tap < 9; ++tap) {
            const int kh = tap / 3, kw = tap % 3;
            const uint32_t arow = sb + SMEM_XU + (kh * 64 + kw + px0) * XU_STRIDE;
            const uint32_t wrow = wub + tap * 16 * WU_STRIDE;
#pragma unroll
            for (int it = 0; it < 8; ++it) {
                uint4 av[4], wv[4];
#pragma unroll
                for (int p = 0; p < 4; ++p)
                    av[p] = *(const uint4*)(smem + (arow - sb) + p * 8 * XU_STRIDE + it * 16);
#pragma unroll
                for (int o = 0; o < 4; ++o)
                    wv[o] = *(const uint4*)(smem + (wrow - sb) + o * WU_STRIDE + it * 16);
#pragma unroll
                for (int p = 0; p < 4; ++p)
#pragma unroll
                    for (int o = 0; o < 4; ++o) {
                        acc[p][o] = __dp4a(av[p].x, wv[o].x, acc[p][o]);
                        acc[p][o] = __dp4a(av[p].y, wv[o].y, acc[p][o]);
                        acc[p][o] = __dp4a(av[p].z, wv[o].z, acc[p][o]);
                        acc[p][o] = __dp4a(av[p].w, wv[o].w, acc[p][o]);
                    }
            }
        }

        __syncthreads();   // join with HMMA warps

        float* s_out = (float*)smem;
#pragma unroll
        for (int p = 0; p < 4; ++p) {
            int m = px0 + 8 * p;
#pragma unroll
            for (int o = 0; o < 4; ++o)
                s_out[(48 + ocg * 4 + o) * OSTR + m] = (float)acc[p][o];
        }
    }
    __syncthreads();

    // ---- Unified store: 64 oc x 2 rows x 14 float4 = 1792 ----
#pragma unroll
    for (int j = 0; j < 5; ++j) {
        int i = t + j * 384;
        if (i >= 1792) break;
        int chunk = i % 14;
        int r     = (i / 14) & 1;
        int oc    = i / 28;
        const float* sp = (const float*)smem + oc * OSTR + r * 64 + chunk * 4;
        float bv = bias[ocbase + oc];
        float4 v = make_float4(sp[0] + bv, sp[1] + bv, sp[2] + bv, sp[3] + bv);
        float* dst = out + (((long long)b * COUT + ocbase + oc) * HW + (h0 + r)) * HW + chunk * 4;
        *(float4*)dst = v;
    }
}

// ---------------------------------------------------------------------------
extern "C" void kernel_launch(void* const* d_in, const int* in_sizes, int n_in,
                              void* d_out, int out_size) {
    const float* x = nullptr;
    const float* pcilt = nullptr;
    const float* bias = nullptr;
    for (int i = 0; i < n_in; ++i) {
        if (in_sizes[i] == COUT) bias = (const float*)d_in[i];
        else if (in_sizes[i] == BATCH * CIN * HW * HW) x = (const float*)d_in[i];
        else pcilt = (const float*)d_in[i];
    }
    float* out = (float*)d_out;

    {
        dim3 g(BATCH * HW, 2);
        pack_x_kernel<<<g, 256>>>(x);
    }
    {
        int n = 9 * COUT * CIN;
        pack_w_kernel<<<(n + 255) / 256, 256>>>(pcilt);
        int n8 = 9 * COUT * 32;
        pack_w8_kernel<<<(n8 + 255) / 256, 256>>>(pcilt);
    }
    {
        cudaFuncSetAttribute(conv_hybrid_kernel,
                             cudaFuncAttributeMaxDynamicSharedMemorySize, SMEM_SZ);
        dim3 grid(COUT / 64, HW / 2, BATCH);   // (4, 28, 16) = 1792 CTAs
        conv_hybrid_kernel<<<grid, 384, SMEM_SZ>>>(bias, out);
    }
    (void)out_size;
}

// round 10
// speedup vs baseline: 1.6533x; 1.6533x over previous
#include <cuda_runtime.h>
#include <cuda_fp16.h>
#include <cstdint>

#define BATCH 16
#define CIN   128
#define COUT  256
#define HW    56

__device__ __align__(16) __half g_xh[BATCH * HW * HW * CIN]; // NHWC fp16 (12.8MB)
__device__ __align__(16) __half g_wh[9 * COUT * CIN];        // [tap][o][c] fp16

__device__ __forceinline__ uint32_t smem_u32(const void* p) {
    uint32_t a;
    asm("{ .reg .u64 t; cvta.to.shared.u64 t, %1; cvt.u32.u64 %0, t; }" : "=r"(a) : "l"(p));
    return a;
}

// ---------------------------------------------------------------------------
// Kernel 1: x NCHW f32 -> NHWC fp16 quantized. 32-ch quarters, 128 threads,
// 3584 blocks for latency hiding.
// ---------------------------------------------------------------------------
__global__ void __launch_bounds__(128) pack_x_kernel(const float* __restrict__ x) {
    __shared__ float tile[32][60];
    const int b = blockIdx.x / HW, h = blockIdx.x % HW;
    const int ch0 = blockIdx.y * 32;
    const int t = threadIdx.x;
#pragma unroll
    for (int j = 0; j < 4; ++j) {              // 448 float4 loads, 3.5/thread
        int idx = t + j * 128;
        if (idx >= 32 * 14) break;
        int c = idx / 14, f4 = idx % 14;
        float4 v = *(const float4*)&x[((b * CIN + ch0 + c) * HW + h) * HW + f4 * 4];
        tile[c][f4 * 4 + 0] = v.x; tile[c][f4 * 4 + 1] = v.y;
        tile[c][f4 * 4 + 2] = v.z; tile[c][f4 * 4 + 3] = v.w;
    }
    __syncthreads();
#pragma unroll
    for (int j = 0; j < 2; ++j) {              // 224 = 4 chunks * 56 w, w-major
        int i = t + j * 128;
        if (i >= HW * 4) break;
        int chunk = i / HW, w = i % HW;
        int c0 = chunk * 8;
        uint4 vv;
        unsigned* pv = (unsigned*)&vv;
#pragma unroll
        for (int k = 0; k < 4; ++k) {
            float q0 = rintf(tile[c0 + 2 * k][w] * 255.0f);
            float q1 = rintf(tile[c0 + 2 * k + 1][w] * 255.0f);
            q0 = fminf(fmaxf(q0, 0.0f), 255.0f);
            q1 = fminf(fmaxf(q1, 0.0f), 255.0f);
            __half2 h2 = __floats2half2_rn(q0, q1);
            pv[k] = *(unsigned*)&h2;
        }
        *(uint4*)&g_xh[((b * HW + h) * HW + w) * CIN + ch0 + c0] = vv;
    }
}

// ---------------------------------------------------------------------------
// Kernel 2: pcilt[...,1] -> [tap][o][c] fp16
// ---------------------------------------------------------------------------
__global__ void pack_w_kernel(const float* __restrict__ pcilt) {
    int idx = blockIdx.x * 256 + threadIdx.x;
    if (idx >= 9 * COUT * CIN) return;
    int c   = idx % CIN;
    int o   = (idx / CIN) % COUT;
    int tap = idx / (CIN * COUT);
    long long p = (((long long)(o * CIN + c)) * 9 + tap) * 256 + 1;
    g_wh[(tap * COUT + o) * CIN + c] = __float2half_rn(pcilt[p]);
}

// ---------------------------------------------------------------------------
// Kernel 3: fp16 HMMA implicit-GEMM conv. CTA = M128 x N64, 8 warps (32x32),
// 2-slot mbarrier W ring, fragment double-buffering (LDSM ks+1 ahead of
// HMMA ks) to kill LDSM->HMMA dependency bubbles. 2 CTAs/SM.
// ---------------------------------------------------------------------------
#define SX_STRIDE 272
#define SX_ROWS   258
#define SW_STRIDE 272
#define SMEM_SX   0
#define SMEM_W0   (SX_ROWS * SX_STRIDE)            // 70176
#define W_SLOT_SZ (64 * SW_STRIDE)                 // 17408
#define SMEM_MB   (SMEM_W0 + 2 * W_SLOT_SZ)        // 104992
#define SMEM_SZ   (SMEM_MB + 64)                   // 105056
#define OSTR      132

__device__ __forceinline__ void hmma(float* c, unsigned a0, unsigned a1, unsigned a2, unsigned a3,
                                     unsigned b0, unsigned b1) {
    asm volatile(
        "mma.sync.aligned.m16n8k16.row.col.f32.f16.f16.f32 "
        "{%0,%1,%2,%3}, {%4,%5,%6,%7}, {%8,%9}, {%0,%1,%2,%3};"
        : "+f"(c[0]), "+f"(c[1]), "+f"(c[2]), "+f"(c[3])
        : "r"(a0), "r"(a1), "r"(a2), "r"(a3), "r"(b0), "r"(b1));
}
#define LDSM4(r0, r1, r2, r3, addr) \
    asm volatile("ldmatrix.sync.aligned.m8n8.x4.shared.b16 {%0,%1,%2,%3}, [%4];" \
        : "=r"(r0), "=r"(r1), "=r"(r2), "=r"(r3) : "r"(addr))
#define CPASYNC(dst, src, sz) \
    asm volatile("cp.async.cg.shared.global [%0], [%1], 16, %2;" :: "r"(dst), "l"(src), "r"(sz))
#define MBAR_INIT(a, n) asm volatile("mbarrier.init.shared.b64 [%0], %1;" :: "r"(a), "r"(n) : "memory")
#define MBAR_ARRIVE(a)  asm volatile("mbarrier.arrive.shared.b64 _, [%0];" :: "r"(a) : "memory")
#define CP_MBAR_ARRIVE(a) \
    asm volatile("cp.async.mbarrier.arrive.noinc.shared.b64 [%0];" :: "r"(a) : "memory")
#define MBAR_WAIT(a, ph) do {                                                     \
    uint32_t _m = (a), _p = (uint32_t)(ph), _d;                                   \
    asm volatile("{ .reg .pred p; mbarrier.try_wait.parity.acquire.cta.shared::cta.b64 p, [%1], %2; selp.b32 %0,1,0,p; }" \
        : "=r"(_d) : "r"(_m), "r"(_p) : "memory");                                \
    if (!_d) {                                                                    \
        asm volatile("{ .reg .pred P1; WL_%=: mbarrier.try_wait.parity.acquire.cta.shared::cta.b64 P1, [%0], %1, 0x989680;" \
            " @P1 bra.uni WD_%=; bra.uni WL_%=; WD_%=: }" :: "r"(_m), "r"(_p) : "memory"); \
    } } while (0)

__global__ void __launch_bounds__(256, 2)
conv_hmma_kernel(const float* __restrict__ bias, float* __restrict__ out) {
    extern __shared__ __align__(16) unsigned char smem[];
    const uint32_t sb = smem_u32(smem);

    const int t    = threadIdx.x;
    const int wid  = t >> 5;
    const int lane = t & 31;
    const int ocbase = blockIdx.x * 64;
    const int h0     = blockIdx.y * 2;
    const int b      = blockIdx.z;

    const uint32_t mb_full  = sb + SMEM_MB;
    const uint32_t mb_empty = sb + SMEM_MB + 16;

    if (t == 0) {
#pragma unroll
        for (int s = 0; s < 2; ++s) {
            MBAR_INIT(mb_full + s * 8, 256);
            MBAR_INIT(mb_empty + s * 8, 256);
        }
    }
    __syncthreads();

    // ---- Prologue: A tile + W taps 0,1 into slots 0,1 ----
    for (int i = t; i < SX_ROWS * 16; i += 256) {
        int pixel = i >> 4, chunk = i & 15;
        int irow = pixel >> 6, col = pixel & 63;
        int h_in = h0 + irow - 1, w_in = col - 1;
        bool ok = (pixel < 256) && (h_in >= 0) && (h_in < HW) && (w_in >= 0) && (w_in < HW);
        const __half* src = ok ? &g_xh[((b * HW + h_in) * HW + w_in) * CIN + chunk * 8] : g_xh;
        CPASYNC(sb + SMEM_SX + pixel * SX_STRIDE + chunk * 16, src, ok ? 16 : 0);
    }
#pragma unroll
    for (int tap = 0; tap < 2; ++tap) {
        uint32_t wdst = sb + SMEM_W0 + tap * W_SLOT_SZ;
#pragma unroll
        for (int j = 0; j < 4; ++j) {
            int i = t + j * 256;
            int o = i >> 4, chunk = i & 15;
            CPASYNC(wdst + o * SW_STRIDE + chunk * 16,
                    &g_wh[(tap * COUT + ocbase + o) * CIN + chunk * 8], 16);
        }
        CP_MBAR_ARRIVE(mb_full + tap * 8);
    }

    const int wm = (wid >> 1) * 32;
    const int wn = (wid & 1) * 32;

    float acc[2][4][4];
#pragma unroll
    for (int mt = 0; mt < 2; ++mt)
#pragma unroll
        for (int nt = 0; nt < 4; ++nt)
#pragma unroll
            for (int k = 0; k < 4; ++k) acc[mt][nt][k] = 0.0f;

    const int g = lane >> 3;
    const int a_lane = (((g & 1) * 8) + (lane & 7)) * SX_STRIDE + (g >> 1) * 16;
    const int b_lane = (((g >> 1) * 8) + (lane & 7)) * SW_STRIDE + (g & 1) * 16;

#pragma unroll 1
    for (int tap = 0; tap < 9; ++tap) {
        const int kh = tap / 3, kw = tap % 3;
        const int slot = tap & 1;
        const uint32_t swc = sb + SMEM_W0 + slot * W_SLOT_SZ;
        const uint32_t abase = sb + SMEM_SX + (kh * 64 + kw + wm) * SX_STRIDE + a_lane;
        const uint32_t bbase = swc + wn * SW_STRIDE + b_lane;

        MBAR_WAIT(mb_full + slot * 8, (tap >> 1) & 1);

        // Double-buffered fragments: LDSM for ks+1 issued before HMMA for ks.
        unsigned a[2][2][4], bf[2][4][2];
        LDSM4(a[0][0][0], a[0][0][1], a[0][0][2], a[0][0][3], abase);
        LDSM4(a[0][1][0], a[0][1][1], a[0][1][2], a[0][1][3], abase + 16 * SX_STRIDE);
        LDSM4(bf[0][0][0], bf[0][0][1], bf[0][1][0], bf[0][1][1], bbase);
        LDSM4(bf[0][2][0], bf[0][2][1], bf[0][3][0], bf[0][3][1], bbase + 16 * SW_STRIDE);

#pragma unroll
        for (int ks = 0; ks < 8; ++ks) {
            const int cur = ks & 1, nxt = cur ^ 1;
            if (ks < 7) {
                const int koff = (ks + 1) * 32;
                LDSM4(a[nxt][0][0], a[nxt][0][1], a[nxt][0][2], a[nxt][0][3], abase + koff);
                LDSM4(a[nxt][1][0], a[nxt][1][1], a[nxt][1][2], a[nxt][1][3],
                      abase + 16 * SX_STRIDE + koff);
                LDSM4(bf[nxt][0][0], bf[nxt][0][1], bf[nxt][1][0], bf[nxt][1][1], bbase + koff);
                LDSM4(bf[nxt][2][0], bf[nxt][2][1], bf[nxt][3][0], bf[nxt][3][1],
                      bbase + 16 * SW_STRIDE + koff);
            }
#pragma unroll
            for (int mt = 0; mt < 2; ++mt)
#pragma unroll
                for (int nt = 0; nt < 4; ++nt)
                    hmma(acc[mt][nt], a[cur][mt][0], a[cur][mt][1], a[cur][mt][2], a[cur][mt][3],
                         bf[cur][nt][0], bf[cur][nt][1]);
        }

        MBAR_ARRIVE(mb_empty + slot * 8);

        // Prefetch tap+2 into the slot just consumed
        if (tap <= 6) {
            MBAR_WAIT(mb_empty + slot * 8, (tap >> 1) & 1);
            uint32_t wdst = sb + SMEM_W0 + slot * W_SLOT_SZ;
#pragma unroll
            for (int j = 0; j < 4; ++j) {
                int i = t + j * 256;
                int o = i >> 4, chunk = i & 15;
                CPASYNC(wdst + o * SW_STRIDE + chunk * 16,
                        &g_wh[((tap + 2) * COUT + ocbase + o) * CIN + chunk * 8], 16);
            }
            CP_MBAR_ARRIVE(mb_full + slot * 8);
        }
    }

    __syncthreads();   // all warps done with A region before epilogue reuse

    // ---- Epilogue: transpose via smem -> coalesced NCHW float4 stores ----
    float* s_out = (float*)smem;
#pragma unroll
    for (int mt = 0; mt < 2; ++mt)
#pragma unroll
        for (int nt = 0; nt < 4; ++nt) {
            int row = wm + mt * 16 + (lane >> 2);
            int col = wn + nt * 8 + (lane & 3) * 2;
            s_out[col * OSTR + row]           = acc[mt][nt][0];
            s_out[(col + 1) * OSTR + row]     = acc[mt][nt][1];
            s_out[col * OSTR + row + 8]       = acc[mt][nt][2];
            s_out[(col + 1) * OSTR + row + 8] = acc[mt][nt][3];
        }
    __syncthreads();

#pragma unroll
    for (int j = 0; j < 7; ++j) {
        int i = t + j * 256;
        int chunk = i % 14;
        int r     = (i / 14) & 1;
        int oc    = i / 28;
        const float* sp = &s_out[oc * OSTR + r * 64 + chunk * 4];
        float bv = bias[ocbase + oc];
        float4 v = make_float4(sp[0] + bv, sp[1] + bv, sp[2] + bv, sp[3] + bv);
        float* dst = out + (((long long)b * COUT + ocbase + oc) * HW + (h0 + r)) * HW + chunk * 4;
        *(float4*)dst = v;
    }
}

// ---------------------------------------------------------------------------
extern "C" void kernel_launch(void* const* d_in, const int* in_sizes, int n_in,
                              void* d_out, int out_size) {
    const float* x = nullptr;
    const float* pcilt = nullptr;
    const float* bias = nullptr;
    for (int i = 0; i < n_in; ++i) {
        if (in_sizes[i] == COUT) bias = (const float*)d_in[i];
        else if (in_sizes[i] == BATCH * CIN * HW * HW) x = (const float*)d_in[i];
        else pcilt = (const float*)d_in[i];
    }
    float* out = (float*)d_out;

    {
        dim3 g(BATCH * HW, 4);
        pack_x_kernel<<<g, 128>>>(x);
    }
    {
        int n = 9 * COUT * CIN;
        pack_w_kernel<<<(n + 255) / 256, 256>>>(pcilt);
    }
    {
        cudaFuncSetAttribute(conv_hmma_kernel,
                             cudaFuncAttributeMaxDynamicSharedMemorySize, SMEM_SZ);
        dim3 grid(COUT / 64, HW / 2, BATCH);   // (4, 28, 16) = 1792 CTAs
        conv_hmma_kernel<<<grid, 256, SMEM_SZ>>>(bias, out);
    }
    (void)out_size;
}

// round 11
// speedup vs baseline: 1.7580x; 1.0634x over previous
#include <cuda_runtime.h>
#include <cuda_fp16.h>
#include <cstdint>

#define BATCH 16
#define CIN   128
#define COUT  256
#define HW    56

__device__ __align__(16) __half g_xh[BATCH * HW * HW * CIN]; // NHWC fp16 (12.8MB)
__device__ __align__(16) __half g_wh[9 * COUT * CIN];        // [tap][o][c] fp16

__device__ __forceinline__ uint32_t smem_u32(const void* p) {
    uint32_t a;
    asm("{ .reg .u64 t; cvta.to.shared.u64 t, %1; cvt.u32.u64 %0, t; }" : "=r"(a) : "l"(p));
    return a;
}

// ---------------------------------------------------------------------------
// Kernel 1: x NCHW f32 -> NHWC fp16 quantized (unchanged from R10)
// ---------------------------------------------------------------------------
__global__ void __launch_bounds__(128) pack_x_kernel(const float* __restrict__ x) {
    __shared__ float tile[32][60];
    const int b = blockIdx.x / HW, h = blockIdx.x % HW;
    const int ch0 = blockIdx.y * 32;
    const int t = threadIdx.x;
#pragma unroll
    for (int j = 0; j < 4; ++j) {
        int idx = t + j * 128;
        if (idx >= 32 * 14) break;
        int c = idx / 14, f4 = idx % 14;
        float4 v = *(const float4*)&x[((b * CIN + ch0 + c) * HW + h) * HW + f4 * 4];
        tile[c][f4 * 4 + 0] = v.x; tile[c][f4 * 4 + 1] = v.y;
        tile[c][f4 * 4 + 2] = v.z; tile[c][f4 * 4 + 3] = v.w;
    }
    __syncthreads();
#pragma unroll
    for (int j = 0; j < 2; ++j) {
        int i = t + j * 128;
        if (i >= HW * 4) break;
        int chunk = i / HW, w = i % HW;
        int c0 = chunk * 8;
        uint4 vv;
        unsigned* pv = (unsigned*)&vv;
#pragma unroll
        for (int k = 0; k < 4; ++k) {
            float q0 = rintf(tile[c0 + 2 * k][w] * 255.0f);
            float q1 = rintf(tile[c0 + 2 * k + 1][w] * 255.0f);
            q0 = fminf(fmaxf(q0, 0.0f), 255.0f);
            q1 = fminf(fmaxf(q1, 0.0f), 255.0f);
            __half2 h2 = __floats2half2_rn(q0, q1);
            pv[k] = *(unsigned*)&h2;
        }
        *(uint4*)&g_xh[((b * HW + h) * HW + w) * CIN + ch0 + c0] = vv;
    }
}

// ---------------------------------------------------------------------------
// Kernel 2: pcilt[...,1] -> [tap][o][c] fp16
// ---------------------------------------------------------------------------
__global__ void pack_w_kernel(const float* __restrict__ pcilt) {
    int idx = blockIdx.x * 256 + threadIdx.x;
    if (idx >= 9 * COUT * CIN) return;
    int c   = idx % CIN;
    int o   = (idx / CIN) % COUT;
    int tap = idx / (CIN * COUT);
    long long p = (((long long)(o * CIN + c)) * 9 + tap) * 256 + 1;
    g_wh[(tap * COUT + o) * CIN + c] = __float2half_rn(pcilt[p]);
}

// ---------------------------------------------------------------------------
// Kernel 3: role-swapped HMMA implicit-GEMM conv.
//   A (GEMM M=128) = weights (oc), linear smem; B (GEMM N=112) = pixels,
//   per-lane ldmatrix row addresses -> ZERO padded MMA work.
//   8 warps: 4 in M (32 oc) x 2 in N (56 px). Direct NCHW float2 epilogue.
// ---------------------------------------------------------------------------
#define PXS       272                              // X pixel-row stride (bytes)
#define X_PX      232                              // 4 input rows x 58 cols
#define WST       272                              // W oc-row stride
#define SMEM_SX   0
#define SMEM_W0   (X_PX * PXS)                     // 63104
#define W_SLOT_SZ (128 * WST)                      // 34816
#define SMEM_MB   (SMEM_W0 + 2 * W_SLOT_SZ)        // 132736
#define SMEM_SZ   (SMEM_MB + 64)

__device__ __forceinline__ void hmma(float* c, unsigned a0, unsigned a1, unsigned a2, unsigned a3,
                                     unsigned b0, unsigned b1) {
    asm volatile(
        "mma.sync.aligned.m16n8k16.row.col.f32.f16.f16.f32 "
        "{%0,%1,%2,%3}, {%4,%5,%6,%7}, {%8,%9}, {%0,%1,%2,%3};"
        : "+f"(c[0]), "+f"(c[1]), "+f"(c[2]), "+f"(c[3])
        : "r"(a0), "r"(a1), "r"(a2), "r"(a3), "r"(b0), "r"(b1));
}
#define LDSM4(r0, r1, r2, r3, addr) \
    asm volatile("ldmatrix.sync.aligned.m8n8.x4.shared.b16 {%0,%1,%2,%3}, [%4];" \
        : "=r"(r0), "=r"(r1), "=r"(r2), "=r"(r3) : "r"(addr))
#define LDSM2(r0, r1, addr) \
    asm volatile("ldmatrix.sync.aligned.m8n8.x2.shared.b16 {%0,%1}, [%2];" \
        : "=r"(r0), "=r"(r1) : "r"(addr))
#define CPASYNC(dst, src, sz) \
    asm volatile("cp.async.cg.shared.global [%0], [%1], 16, %2;" :: "r"(dst), "l"(src), "r"(sz))
#define MBAR_INIT(a, n) asm volatile("mbarrier.init.shared.b64 [%0], %1;" :: "r"(a), "r"(n) : "memory")
#define MBAR_ARRIVE(a)  asm volatile("mbarrier.arrive.shared.b64 _, [%0];" :: "r"(a) : "memory")
#define CP_MBAR_ARRIVE(a) \
    asm volatile("cp.async.mbarrier.arrive.noinc.shared.b64 [%0];" :: "r"(a) : "memory")
#define MBAR_WAIT(a, ph) do {                                                     \
    uint32_t _m = (a), _p = (uint32_t)(ph), _d;                                   \
    asm volatile("{ .reg .pred p; mbarrier.try_wait.parity.acquire.cta.shared::cta.b64 p, [%1], %2; selp.b32 %0,1,0,p; }" \
        : "=r"(_d) : "r"(_m), "r"(_p) : "memory");                                \
    if (!_d) {                                                                    \
        asm volatile("{ .reg .pred P1; WL_%=: mbarrier.try_wait.parity.acquire.cta.shared::cta.b64 P1, [%0], %1, 0x989680;" \
            " @P1 bra.uni WD_%=; bra.uni WL_%=; WD_%=: }" :: "r"(_m), "r"(_p) : "memory"); \
    } } while (0)

__global__ void __launch_bounds__(256, 1)
conv_hmma_kernel(const float* __restrict__ bias, float* __restrict__ out) {
    extern __shared__ __align__(16) unsigned char smem[];
    const uint32_t sb = smem_u32(smem);

    const int t    = threadIdx.x;
    const int wid  = t >> 5;
    const int lane = t & 31;
    const int ocbase = blockIdx.x * 128;      // GEMM-M tile (oc)
    const int h0     = blockIdx.y * 2;        // output row pair
    const int b      = blockIdx.z;

    const uint32_t mb_full  = sb + SMEM_MB;
    const uint32_t mb_empty = sb + SMEM_MB + 16;

    if (t == 0) {
#pragma unroll
        for (int s = 0; s < 2; ++s) {
            MBAR_INIT(mb_full + s * 8, 256);
            MBAR_INIT(mb_empty + s * 8, 256);
        }
    }
    __syncthreads();

    // ---- Prologue: X halo tile (232 px) + W taps 0,1 into slots 0,1 ----
    for (int i = t; i < X_PX * 16; i += 256) {
        int px = i >> 4, chunk = i & 15;
        int row = px / 58, col = px % 58;
        int h_in = h0 + row - 1, w_in = col - 1;
        bool ok = (h_in >= 0) && (h_in < HW) && (w_in >= 0) && (w_in < HW);
        const __half* src = ok ? &g_xh[((b * HW + h_in) * HW + w_in) * CIN + chunk * 8] : g_xh;
        CPASYNC(sb + SMEM_SX + px * PXS + chunk * 16, src, ok ? 16 : 0);
    }
#pragma unroll
    for (int tap = 0; tap < 2; ++tap) {
        uint32_t wdst = sb + SMEM_W0 + tap * W_SLOT_SZ;
#pragma unroll
        for (int j = 0; j < 8; ++j) {
            int i = t + j * 256;
            int o = i >> 4, chunk = i & 15;
            CPASYNC(wdst + o * WST + chunk * 16,
                    &g_wh[(tap * COUT + ocbase + o) * CIN + chunk * 8], 16);
        }
        CP_MBAR_ARRIVE(mb_full + tap * 8);
    }

    const int wm = (wid >> 1) * 32;          // warp oc offset (0/32/64/96)
    const int wn = (wid & 1) * 56;           // warp pixel offset (0/56)

    float acc[2][7][4];
#pragma unroll
    for (int mt = 0; mt < 2; ++mt)
#pragma unroll
        for (int nt = 0; nt < 7; ++nt)
#pragma unroll
            for (int k = 0; k < 4; ++k) acc[mt][nt][k] = 0.0f;

    const int g = lane >> 3;
    // A (weights): linear rows. matrices: {rows0-7, rows8-15, +16B x2}
    const int a_lane = (((g & 1) * 8) + (lane & 7)) * WST + (g >> 1) * 16;
    // B (pixels): per-lane halo address. LDSM4 pair base T: tiles T,T+1.
    auto px_addr = [&](int px) -> uint32_t {
        int r = px / 56, w = px % 56;
        return sb + SMEM_SX + (uint32_t)(r * 58 + w) * PXS;
    };
    const int pxl = (lane & 7);
    const uint32_t bp0 = px_addr(wn + ((g >> 1) + 0) * 8 + pxl) + (g & 1) * 16;
    const uint32_t bp1 = px_addr(wn + ((g >> 1) + 2) * 8 + pxl) + (g & 1) * 16;
    const uint32_t bp2 = px_addr(wn + ((g >> 1) + 4) * 8 + pxl) + (g & 1) * 16;
    const uint32_t bp3 = px_addr(wn + 48 + pxl) + ((lane >> 3) & 1) * 16;  // LDSM2: lanes 0-15

#pragma unroll 1
    for (int tap = 0; tap < 9; ++tap) {
        const int kh = tap / 3, kw = tap % 3;
        const int slot = tap & 1;
        const uint32_t aw = sb + SMEM_W0 + slot * W_SLOT_SZ + wm * WST + a_lane;
        const uint32_t toff = (uint32_t)(kh * 58 + kw) * PXS;

        MBAR_WAIT(mb_full + slot * 8, (tap >> 1) & 1);

        unsigned a[2][2][4], bf[2][7][2];
        // preload ks=0 fragments
        LDSM4(a[0][0][0], a[0][0][1], a[0][0][2], a[0][0][3], aw);
        LDSM4(a[0][1][0], a[0][1][1], a[0][1][2], a[0][1][3], aw + 16 * WST);
        LDSM4(bf[0][0][0], bf[0][0][1], bf[0][1][0], bf[0][1][1], bp0 + toff);
        LDSM4(bf[0][2][0], bf[0][2][1], bf[0][3][0], bf[0][3][1], bp1 + toff);
        LDSM4(bf[0][4][0], bf[0][4][1], bf[0][5][0], bf[0][5][1], bp2 + toff);
        LDSM2(bf[0][6][0], bf[0][6][1], bp3 + toff);

#pragma unroll
        for (int ks = 0; ks < 8; ++ks) {
            const int cur = ks & 1, nxt = cur ^ 1;
            if (ks < 7) {
                const int koff = (ks + 1) * 32;
                LDSM4(a[nxt][0][0], a[nxt][0][1], a[nxt][0][2], a[nxt][0][3], aw + koff);
                LDSM4(a[nxt][1][0], a[nxt][1][1], a[nxt][1][2], a[nxt][1][3],
                      aw + 16 * WST + koff);
                LDSM4(bf[nxt][0][0], bf[nxt][0][1], bf[nxt][1][0], bf[nxt][1][1],
                      bp0 + toff + koff);
                LDSM4(bf[nxt][2][0], bf[nxt][2][1], bf[nxt][3][0], bf[nxt][3][1],
                      bp1 + toff + koff);
                LDSM4(bf[nxt][4][0], bf[nxt][4][1], bf[nxt][5][0], bf[nxt][5][1],
                      bp2 + toff + koff);
                LDSM2(bf[nxt][6][0], bf[nxt][6][1], bp3 + toff + koff);
            }
#pragma unroll
            for (int mt = 0; mt < 2; ++mt)
#pragma unroll
                for (int nt = 0; nt < 7; ++nt)
                    hmma(acc[mt][nt], a[cur][mt][0], a[cur][mt][1], a[cur][mt][2], a[cur][mt][3],
                         bf[cur][nt][0], bf[cur][nt][1]);
        }

        MBAR_ARRIVE(mb_empty + slot * 8);

        if (tap <= 6) {
            MBAR_WAIT(mb_empty + slot * 8, (tap >> 1) & 1);
            uint32_t wdst = sb + SMEM_W0 + slot * W_SLOT_SZ;
#pragma unroll
            for (int j = 0; j < 8; ++j) {
                int i = t + j * 256;
                int o = i >> 4, chunk = i & 15;
                CPASYNC(wdst + o * WST + chunk * 16,
                        &g_wh[((tap + 2) * COUT + ocbase + o) * CIN + chunk * 8], 16);
            }
            CP_MBAR_ARRIVE(mb_full + slot * 8);
        }
    }

    // ---- Epilogue: direct NCHW float2 stores (no smem round-trip) ----
    const int r  = wid & 1;                  // output row within pair
    const int hrow = h0 + r;
#pragma unroll
    for (int mt = 0; mt < 2; ++mt) {
        const int oc0 = ocbase + wm + mt * 16 + (lane >> 2);
        const float bv0 = bias[oc0];
        const float bv8 = bias[oc0 + 8];
        float* p0 = out + (((long long)b * COUT + oc0) * HW + hrow) * HW;
        float* p8 = out + (((long long)b * COUT + oc0 + 8) * HW + hrow) * HW;
#pragma unroll
        for (int nt = 0; nt < 7; ++nt) {
            const int w = nt * 8 + (lane & 3) * 2;
            float2 v0 = make_float2(acc[mt][nt][0] + bv0, acc[mt][nt][1] + bv0);
            float2 v8 = make_float2(acc[mt][nt][2] + bv8, acc[mt][nt][3] + bv8);
            *(float2*)(p0 + w) = v0;
            *(float2*)(p8 + w) = v8;
        }
    }
}

// ---------------------------------------------------------------------------
extern "C" void kernel_launch(void* const* d_in, const int* in_sizes, int n_in,
                              void* d_out, int out_size) {
    const float* x = nullptr;
    const float* pcilt = nullptr;
    const float* bias = nullptr;
    for (int i = 0; i < n_in; ++i) {
        if (in_sizes[i] == COUT) bias = (const float*)d_in[i];
        else if (in_sizes[i] == BATCH * CIN * HW * HW) x = (const float*)d_in[i];
        else pcilt = (const float*)d_in[i];
    }
    float* out = (float*)d_out;

    {
        dim3 g(BATCH * HW, 4);
        pack_x_kernel<<<g, 128>>>(x);
    }
    {
        int n = 9 * COUT * CIN;
        pack_w_kernel<<<(n + 255) / 256, 256>>>(pcilt);
    }
    {
        cudaFuncSetAttribute(conv_hmma_kernel,
                             cudaFuncAttributeMaxDynamicSharedMemorySize, SMEM_SZ);
        dim3 grid(COUT / 128, HW / 2, BATCH);   // (2, 28, 16) = 896 CTAs
        conv_hmma_kernel<<<grid, 256, SMEM_SZ>>>(bias, out);
    }
    (void)out_size;
}

// round 12
// speedup vs baseline: 1.7843x; 1.0150x over previous
#include <cuda_runtime.h>
#include <cuda_fp16.h>
#include <cstdint>

#define BATCH 16
#define CIN   128
#define COUT  256
#define HW    56

__device__ __align__(16) __half g_xh[BATCH * HW * HW * CIN]; // NHWC fp16 (12.8MB)
__device__ __align__(16) __half g_wh[9 * COUT * CIN];        // [tap][o][c] fp16

__device__ __forceinline__ uint32_t smem_u32(const void* p) {
    uint32_t a;
    asm("{ .reg .u64 t; cvta.to.shared.u64 t, %1; cvt.u32.u64 %0, t; }" : "=r"(a) : "l"(p));
    return a;
}

// ---------------------------------------------------------------------------
// Kernel 1: x NCHW f32 -> NHWC fp16 quantized
// ---------------------------------------------------------------------------
__global__ void __launch_bounds__(128) pack_x_kernel(const float* __restrict__ x) {
    __shared__ float tile[32][60];
    const int b = blockIdx.x / HW, h = blockIdx.x % HW;
    const int ch0 = blockIdx.y * 32;
    const int t = threadIdx.x;
#pragma unroll
    for (int j = 0; j < 4; ++j) {
        int idx = t + j * 128;
        if (idx >= 32 * 14) break;
        int c = idx / 14, f4 = idx % 14;
        float4 v = *(const float4*)&x[((b * CIN + ch0 + c) * HW + h) * HW + f4 * 4];
        tile[c][f4 * 4 + 0] = v.x; tile[c][f4 * 4 + 1] = v.y;
        tile[c][f4 * 4 + 2] = v.z; tile[c][f4 * 4 + 3] = v.w;
    }
    __syncthreads();
#pragma unroll
    for (int j = 0; j < 2; ++j) {
        int i = t + j * 128;
        if (i >= HW * 4) break;
        int chunk = i / HW, w = i % HW;
        int c0 = chunk * 8;
        uint4 vv;
        unsigned* pv = (unsigned*)&vv;
#pragma unroll
        for (int k = 0; k < 4; ++k) {
            float q0 = rintf(tile[c0 + 2 * k][w] * 255.0f);
            float q1 = rintf(tile[c0 + 2 * k + 1][w] * 255.0f);
            q0 = fminf(fmaxf(q0, 0.0f), 255.0f);
            q1 = fminf(fmaxf(q1, 0.0f), 255.0f);
            __half2 h2 = __floats2half2_rn(q0, q1);
            pv[k] = *(unsigned*)&h2;
        }
        *(uint4*)&g_xh[((b * HW + h) * HW + w) * CIN + ch0 + c0] = vv;
    }
}

// ---------------------------------------------------------------------------
// Kernel 2: pcilt[...,1] -> [tap][o][c] fp16
// ---------------------------------------------------------------------------
__global__ void pack_w_kernel(const float* __restrict__ pcilt) {
    int idx = blockIdx.x * 256 + threadIdx.x;
    if (idx >= 9 * COUT * CIN) return;
    int c   = idx % CIN;
    int o   = (idx / CIN) % COUT;
    int tap = idx / (CIN * COUT);
    long long p = (((long long)(o * CIN + c)) * 9 + tap) * 256 + 1;
    g_wh[(tap * COUT + o) * CIN + c] = __float2half_rn(pcilt[p]);
}

// ---------------------------------------------------------------------------
// Kernel 3: role-swapped HMMA implicit-GEMM conv.
//   A (GEMM M=128) = weights (oc); B (GEMM N=112) = pixels via per-lane
//   ldmatrix addresses (zero padded MMA work). 3-slot W ring, distance-2
//   producer wait -> no per-tap CTA rendezvous. Direct NCHW epilogue.
// ---------------------------------------------------------------------------
#define PXS       272
#define X_PX      232                              // 4 input rows x 58 cols
#define WST       272
#define SMEM_SX   0
#define SMEM_W0   (X_PX * PXS)                     // 63104
#define W_SLOT_SZ (128 * WST)                      // 34816
#define SMEM_MB   (SMEM_W0 + 3 * W_SLOT_SZ)        // 167552
#define SMEM_SZ   (SMEM_MB + 64)

__device__ __forceinline__ void hmma(float* c, unsigned a0, unsigned a1, unsigned a2, unsigned a3,
                                     unsigned b0, unsigned b1) {
    asm volatile(
        "mma.sync.aligned.m16n8k16.row.col.f32.f16.f16.f32 "
        "{%0,%1,%2,%3}, {%4,%5,%6,%7}, {%8,%9}, {%0,%1,%2,%3};"
        : "+f"(c[0]), "+f"(c[1]), "+f"(c[2]), "+f"(c[3])
        : "r"(a0), "r"(a1), "r"(a2), "r"(a3), "r"(b0), "r"(b1));
}
#define LDSM4(r0, r1, r2, r3, addr) \
    asm volatile("ldmatrix.sync.aligned.m8n8.x4.shared.b16 {%0,%1,%2,%3}, [%4];" \
        : "=r"(r0), "=r"(r1), "=r"(r2), "=r"(r3) : "r"(addr))
#define LDSM2(r0, r1, addr) \
    asm volatile("ldmatrix.sync.aligned.m8n8.x2.shared.b16 {%0,%1}, [%2];" \
        : "=r"(r0), "=r"(r1) : "r"(addr))
#define CPASYNC(dst, src, sz) \
    asm volatile("cp.async.cg.shared.global [%0], [%1], 16, %2;" :: "r"(dst), "l"(src), "r"(sz))
#define MBAR_INIT(a, n) asm volatile("mbarrier.init.shared.b64 [%0], %1;" :: "r"(a), "r"(n) : "memory")
#define MBAR_ARRIVE(a)  asm volatile("mbarrier.arrive.shared.b64 _, [%0];" :: "r"(a) : "memory")
#define CP_MBAR_ARRIVE(a) \
    asm volatile("cp.async.mbarrier.arrive.noinc.shared.b64 [%0];" :: "r"(a) : "memory")
#define MBAR_WAIT(a, ph) do {                                                     \
    uint32_t _m = (a), _p = (uint32_t)(ph), _d;                                   \
    asm volatile("{ .reg .pred p; mbarrier.try_wait.parity.acquire.cta.shared::cta.b64 p, [%1], %2; selp.b32 %0,1,0,p; }" \
        : "=r"(_d) : "r"(_m), "r"(_p) : "memory");                                \
    if (!_d) {                                                                    \
        asm volatile("{ .reg .pred P1; WL_%=: mbarrier.try_wait.parity.acquire.cta.shared::cta.b64 P1, [%0], %1, 0x989680;" \
            " @P1 bra.uni WD_%=; bra.uni WL_%=; WD_%=: }" :: "r"(_m), "r"(_p) : "memory"); \
    } } while (0)

__global__ void __launch_bounds__(256, 1)
conv_hmma_kernel(const float* __restrict__ bias, float* __restrict__ out) {
    extern __shared__ __align__(16) unsigned char smem[];
    const uint32_t sb = smem_u32(smem);

    const int t    = threadIdx.x;
    const int wid  = t >> 5;
    const int lane = t & 31;
    const int ocbase = blockIdx.x * 128;
    const int h0     = blockIdx.y * 2;
    const int b      = blockIdx.z;

    const uint32_t mb_full  = sb + SMEM_MB;        // 3 x 8B
    const uint32_t mb_empty = sb + SMEM_MB + 24;   // 3 x 8B

    if (t == 0) {
#pragma unroll
        for (int s = 0; s < 3; ++s) {
            MBAR_INIT(mb_full + s * 8, 256);
            MBAR_INIT(mb_empty + s * 8, 256);
        }
    }
    __syncthreads();

    // ---- Prologue: X halo tile (232 px) + W taps 0,1,2 into slots 0,1,2 ----
    for (int i = t; i < X_PX * 16; i += 256) {
        int px = i >> 4, chunk = i & 15;
        int row = px / 58, col = px % 58;
        int h_in = h0 + row - 1, w_in = col - 1;
        bool ok = (h_in >= 0) && (h_in < HW) && (w_in >= 0) && (w_in < HW);
        const __half* src = ok ? &g_xh[((b * HW + h_in) * HW + w_in) * CIN + chunk * 8] : g_xh;
        CPASYNC(sb + SMEM_SX + px * PXS + chunk * 16, src, ok ? 16 : 0);
    }
#pragma unroll
    for (int tap = 0; tap < 3; ++tap) {
        uint32_t wdst = sb + SMEM_W0 + tap * W_SLOT_SZ;
#pragma unroll
        for (int j = 0; j < 8; ++j) {
            int i = t + j * 256;
            int o = i >> 4, chunk = i & 15;
            CPASYNC(wdst + o * WST + chunk * 16,
                    &g_wh[(tap * COUT + ocbase + o) * CIN + chunk * 8], 16);
        }
        CP_MBAR_ARRIVE(mb_full + tap * 8);
    }

    const int wm = (wid >> 1) * 32;          // warp oc offset
    const int wn = (wid & 1) * 56;           // warp pixel offset

    float acc[2][7][4];
#pragma unroll
    for (int mt = 0; mt < 2; ++mt)
#pragma unroll
        for (int nt = 0; nt < 7; ++nt)
#pragma unroll
            for (int k = 0; k < 4; ++k) acc[mt][nt][k] = 0.0f;

    const int g = lane >> 3;
    const int a_lane = (((g & 1) * 8) + (lane & 7)) * WST + (g >> 1) * 16;
    auto px_addr = [&](int px) -> uint32_t {
        int r = px / 56, w = px % 56;
        return sb + SMEM_SX + (uint32_t)(r * 58 + w) * PXS;
    };
    const int pxl = (lane & 7);
    const uint32_t bp0 = px_addr(wn + ((g >> 1) + 0) * 8 + pxl) + (g & 1) * 16;
    const uint32_t bp1 = px_addr(wn + ((g >> 1) + 2) * 8 + pxl) + (g & 1) * 16;
    const uint32_t bp2 = px_addr(wn + ((g >> 1) + 4) * 8 + pxl) + (g & 1) * 16;
    const uint32_t bp3 = px_addr(wn + 48 + pxl) + ((lane >> 3) & 1) * 16;

    int slot = 0, cons_ph = 0;

#pragma unroll 1
    for (int tap = 0; tap < 9; ++tap) {
        const int kh = tap / 3, kw = tap % 3;
        const uint32_t aw = sb + SMEM_W0 + slot * W_SLOT_SZ + wm * WST + a_lane;
        const uint32_t toff = (uint32_t)(kh * 58 + kw) * PXS;

        MBAR_WAIT(mb_full + slot * 8, cons_ph);

        unsigned a[2][2][4], bf[2][7][2];
        LDSM4(a[0][0][0], a[0][0][1], a[0][0][2], a[0][0][3], aw);
        LDSM4(a[0][1][0], a[0][1][1], a[0][1][2], a[0][1][3], aw + 16 * WST);
        LDSM4(bf[0][0][0], bf[0][0][1], bf[0][1][0], bf[0][1][1], bp0 + toff);
        LDSM4(bf[0][2][0], bf[0][2][1], bf[0][3][0], bf[0][3][1], bp1 + toff);
        LDSM4(bf[0][4][0], bf[0][4][1], bf[0][5][0], bf[0][5][1], bp2 + toff);
        LDSM2(bf[0][6][0], bf[0][6][1], bp3 + toff);

#pragma unroll
        for (int ks = 0; ks < 8; ++ks) {
            const int cur = ks & 1, nxt = cur ^ 1;
            if (ks < 7) {
                const int koff = (ks + 1) * 32;
                LDSM4(a[nxt][0][0], a[nxt][0][1], a[nxt][0][2], a[nxt][0][3], aw + koff);
                LDSM4(a[nxt][1][0], a[nxt][1][1], a[nxt][1][2], a[nxt][1][3],
                      aw + 16 * WST + koff);
                LDSM4(bf[nxt][0][0], bf[nxt][0][1], bf[nxt][1][0], bf[nxt][1][1],
                      bp0 + toff + koff);
                LDSM4(bf[nxt][2][0], bf[nxt][2][1], bf[nxt][3][0], bf[nxt][3][1],
                      bp1 + toff + koff);
                LDSM4(bf[nxt][4][0], bf[nxt][4][1], bf[nxt][5][0], bf[nxt][5][1],
                      bp2 + toff + koff);
                LDSM2(bf[nxt][6][0], bf[nxt][6][1], bp3 + toff + koff);
            }
#pragma unroll
            for (int mt = 0; mt < 2; ++mt)
#pragma unroll
                for (int nt = 0; nt < 7; ++nt)
                    hmma(acc[mt][nt], a[cur][mt][0], a[cur][mt][1], a[cur][mt][2], a[cur][mt][3],
                         bf[cur][nt][0], bf[cur][nt][1]);
        }

        MBAR_ARRIVE(mb_empty + slot * 8);

        // Prefetch tap+2 into slot (tap+2)%3 — consumed at tap-1, so the
        // empty-wait only rendezvouses with tap-1's readers (skew <= 1 tap).
        if (tap >= 1 && tap <= 6) {
            const int ws = (slot + 2 >= 3) ? slot - 1 : slot + 2;
            const int pph = ((tap - 1) / 3) & 1;
            MBAR_WAIT(mb_empty + ws * 8, pph);
            uint32_t wdst = sb + SMEM_W0 + ws * W_SLOT_SZ;
#pragma unroll
            for (int j = 0; j < 8; ++j) {
                int i = t + j * 256;
                int o = i >> 4, chunk = i & 15;
                CPASYNC(wdst + o * WST + chunk * 16,
                        &g_wh[((tap + 2) * COUT + ocbase + o) * CIN + chunk * 8], 16);
            }
            CP_MBAR_ARRIVE(mb_full + ws * 8);
        }

        slot = (slot + 1 == 3) ? 0 : slot + 1;
        if (tap == 2 || tap == 5) cons_ph ^= 1;
    }

    // ---- Epilogue: direct NCHW float2 stores ----
    const int r  = wid & 1;
    const int hrow = h0 + r;
#pragma unroll
    for (int mt = 0; mt < 2; ++mt) {
        const int oc0 = ocbase + wm + mt * 16 + (lane >> 2);
        const float bv0 = bias[oc0];
        const float bv8 = bias[oc0 + 8];
        float* p0 = out + (((long long)b * COUT + oc0) * HW + hrow) * HW;
        float* p8 = out + (((long long)b * COUT + oc0 + 8) * HW + hrow) * HW;
#pragma unroll
        for (int nt = 0; nt < 7; ++nt) {
            const int w = nt * 8 + (lane & 3) * 2;
            float2 v0 = make_float2(acc[mt][nt][0] + bv0, acc[mt][nt][1] + bv0);
            float2 v8 = make_float2(acc[mt][nt][2] + bv8, acc[mt][nt][3] + bv8);
            *(float2*)(p0 + w) = v0;
            *(float2*)(p8 + w) = v8;
        }
    }
}

// ---------------------------------------------------------------------------
extern "C" void kernel_launch(void* const* d_in, const int* in_sizes, int n_in,
                              void* d_out, int out_size) {
    const float* x = nullptr;
    const float* pcilt = nullptr;
    const float* bias = nullptr;
    for (int i = 0; i < n_in; ++i) {
        if (in_sizes[i] == COUT) bias = (const float*)d_in[i];
        else if (in_sizes[i] == BATCH * CIN * HW * HW) x = (const float*)d_in[i];
        else pcilt = (const float*)d_in[i];
    }
    float* out = (float*)d_out;

    {
        dim3 g(BATCH * HW, 4);
        pack_x_kernel<<<g, 128>>>(x);
    }
    {
        int n = 9 * COUT * CIN;
        pack_w_kernel<<<(n + 255) / 256, 256>>>(pcilt);
    }
    {
        cudaFuncSetAttribute(conv_hmma_kernel,
                             cudaFuncAttributeMaxDynamicSharedMemorySize, SMEM_SZ);
        dim3 grid(COUT / 128, HW / 2, BATCH);   // (2, 28, 16) = 896 CTAs
        conv_hmma_kernel<<<grid, 256, SMEM_SZ>>>(bias, out);
    }
    (void)out_size;
}